// round 1
// baseline (speedup 1.0000x reference)
#include <cuda_runtime.h>
#include <math.h>

#define BB 512
#define TT 1024
#define EE 64
#define HH 32
#define PP 720

// ---------------- scratch (device globals: no allocation allowed) ----------
__device__ float g_z0[(size_t)TT * BB * HH];   // [t][b][h]  64 MB
__device__ float g_hT0[BB * HH];
__device__ float g_hT1[BB * HH];
__device__ float g_ts1[(size_t)PP * BB * HH];  // [p][b][h]  45 MB

#define FMA4(acc, vec, wa, base)                  \
    do {                                          \
        acc = fmaf((vec).x, (wa)[(base) + 0], acc); \
        acc = fmaf((vec).y, (wa)[(base) + 1], acc); \
        acc = fmaf((vec).z, (wa)[(base) + 2], acc); \
        acc = fmaf((vec).w, (wa)[(base) + 3], acc); \
    } while (0)

// ============================================================================
// Kernel 1: z0[t][b][h] = dot(x[b][t][:], Wih0[h][:]) + (bih0+bhh0)[h]
// grid 8192 x 256 threads; block handles 64 (b,t) rows (same b, 64 consecutive t)
// ============================================================================
__global__ __launch_bounds__(256) void k_z0(const float* __restrict__ x,
                                            const float* __restrict__ Wih0,
                                            const float* __restrict__ bih0,
                                            const float* __restrict__ bhh0) {
    __shared__ __align__(16) float Xs[64 * EE];   // 16 KB
    __shared__ __align__(16) float Ws[HH * EE];   // 8 KB
    __shared__ float bs[HH];

    const int tid = threadIdx.x;
    const long R0 = (long)blockIdx.x * 64;        // first (b,t) row of tile

    // stage X tile (4096 floats) coalesced
    {
        const float4* src = (const float4*)(x + R0 * EE);
        float4* dst = (float4*)Xs;
#pragma unroll
        for (int i = 0; i < 4; i++) dst[tid + 256 * i] = src[tid + 256 * i];
    }
    // stage W (2048 floats)
    {
        const float4* src = (const float4*)Wih0;
        float4* dst = (float4*)Ws;
#pragma unroll
        for (int i = 0; i < 2; i++) dst[tid + 256 * i] = src[tid + 256 * i];
    }
    if (tid < HH) bs[tid] = bih0[tid] + bhh0[tid];
    __syncthreads();

    const int h = tid & 31;
    const int rbase = tid >> 5;  // 0..7

    float w[EE];
#pragma unroll
    for (int i = 0; i < EE / 4; i++) {
        float4 wv = *(const float4*)&Ws[h * EE + 4 * i];
        w[4 * i + 0] = wv.x; w[4 * i + 1] = wv.y;
        w[4 * i + 2] = wv.z; w[4 * i + 3] = wv.w;
    }
    const float bias = bs[h];

#pragma unroll
    for (int rr = 0; rr < 8; rr++) {
        const int r = rbase + 8 * rr;
        float acc = bias;
#pragma unroll
        for (int e4 = 0; e4 < EE / 4; e4++) {
            float4 xv = *(const float4*)&Xs[r * EE + 4 * e4];  // broadcast
            FMA4(acc, xv, w, 4 * e4);
        }
        const long R = R0 + r;
        const int b = (int)(R >> 10);       // TT = 1024
        const int t = (int)(R & 1023);
        g_z0[((long)t * BB + b) * HH + h] = acc;
    }
}

// ============================================================================
// Kernel 2: encoder 2-layer scan. One warp per batch row. Layer 1 lags layer 0
// by one step so all dot products read stable shared buffers.
// grid 128 x 128 threads (4 warps/block, 512 warps total)
// ============================================================================
__global__ __launch_bounds__(128) void k_enc(const float* __restrict__ Whh0,
                                             const float* __restrict__ Wih1,
                                             const float* __restrict__ Whh1,
                                             const float* __restrict__ bih1,
                                             const float* __restrict__ bhh1) {
    __shared__ __align__(16) float shA[4][HH];  // h0[t-1] broadcast
    __shared__ __align__(16) float shB[4][HH];  // h1[t-2] broadcast

    const int lane = threadIdx.x & 31;
    const int w = threadIdx.x >> 5;
    const int b = blockIdx.x * 4 + w;

    float w0[HH], wi1[HH], wh1[HH];
#pragma unroll
    for (int i = 0; i < HH / 4; i++) {
        float4 v0 = *(const float4*)&Whh0[lane * HH + 4 * i];
        float4 v1 = *(const float4*)&Wih1[lane * HH + 4 * i];
        float4 v2 = *(const float4*)&Whh1[lane * HH + 4 * i];
        w0[4 * i + 0] = v0.x; w0[4 * i + 1] = v0.y; w0[4 * i + 2] = v0.z; w0[4 * i + 3] = v0.w;
        wi1[4 * i + 0] = v1.x; wi1[4 * i + 1] = v1.y; wi1[4 * i + 2] = v1.z; wi1[4 * i + 3] = v1.w;
        wh1[4 * i + 0] = v2.x; wh1[4 * i + 1] = v2.y; wh1[4 * i + 2] = v2.z; wh1[4 * i + 3] = v2.w;
    }
    const float bias1 = bih1[lane] + bhh1[lane];

    shA[w][lane] = 0.0f;
    shB[w][lane] = 0.0f;
    __syncwarp();

    const float* zp = g_z0 + (long)b * HH + lane;
    const int ST = BB * HH;  // 16384

    float zbuf[4];
#pragma unroll
    for (int i = 0; i < 4; i++) zbuf[i] = zp[(long)i * ST];

    float h0 = 0.0f, h1 = 0.0f;

#pragma unroll 4
    for (int t = 0; t < TT; t++) {
        const float z = zbuf[t & 3];
        if (t + 4 < TT) zbuf[t & 3] = zp[(long)(t + 4) * ST];

        float m0a = z, m0b = 0.0f;
        float m1a = bias1, m1b = 0.0f;
        float m2a = 0.0f, m2b = 0.0f;
#pragma unroll
        for (int k8 = 0; k8 < 4; k8++) {
            float4 a0 = *(const float4*)&shA[w][8 * k8 + 0];
            float4 a1 = *(const float4*)&shA[w][8 * k8 + 4];
            float4 c0 = *(const float4*)&shB[w][8 * k8 + 0];
            float4 c1 = *(const float4*)&shB[w][8 * k8 + 4];
            FMA4(m0a, a0, w0, 8 * k8);     FMA4(m0b, a1, w0, 8 * k8 + 4);
            FMA4(m1a, a0, wi1, 8 * k8);    FMA4(m1b, a1, wi1, 8 * k8 + 4);
            FMA4(m2a, c0, wh1, 8 * k8);    FMA4(m2b, c1, wh1, 8 * k8 + 4);
        }
        h0 = tanhf(m0a + m0b);
        h1 = (t > 0) ? tanhf(m1a + m1b + m2a + m2b) : 0.0f;  // h1[t-1]; h1[-1]=0

        __syncwarp();                // all lanes done reading shA/shB
        shA[w][lane] = h0;           // h0[t]
        shB[w][lane] = h1;           // h1[t-1]
        __syncwarp();                // visible for next iter
    }

    // epilogue: h1[T-1] from shA=h0[T-1], shB=h1[T-2]
    {
        float m1a = bias1, m1b = 0.0f, m2a = 0.0f, m2b = 0.0f;
#pragma unroll
        for (int k8 = 0; k8 < 4; k8++) {
            float4 a0 = *(const float4*)&shA[w][8 * k8 + 0];
            float4 a1 = *(const float4*)&shA[w][8 * k8 + 4];
            float4 c0 = *(const float4*)&shB[w][8 * k8 + 0];
            float4 c1 = *(const float4*)&shB[w][8 * k8 + 4];
            FMA4(m1a, a0, wi1, 8 * k8);    FMA4(m1b, a1, wi1, 8 * k8 + 4);
            FMA4(m2a, c0, wh1, 8 * k8);    FMA4(m2b, c1, wh1, 8 * k8 + 4);
        }
        g_hT0[b * HH + lane] = h0;
        g_hT1[b * HH + lane] = tanhf(m1a + m1b + m2a + m2b);
    }
}

// ============================================================================
// Kernel 3: transition 2-layer scan (constant layer-0 input = bias).
// Same lag structure; writes ts1[p][b][h].
// ============================================================================
__global__ __launch_bounds__(128) void k_trans(const float* __restrict__ Whh0,
                                               const float* __restrict__ bih0,
                                               const float* __restrict__ bhh0,
                                               const float* __restrict__ Wih1,
                                               const float* __restrict__ Whh1,
                                               const float* __restrict__ bih1,
                                               const float* __restrict__ bhh1) {
    __shared__ __align__(16) float shA[4][HH];
    __shared__ __align__(16) float shB[4][HH];

    const int lane = threadIdx.x & 31;
    const int w = threadIdx.x >> 5;
    const int b = blockIdx.x * 4 + w;

    float w0[HH], wi1[HH], wh1[HH];
#pragma unroll
    for (int i = 0; i < HH / 4; i++) {
        float4 v0 = *(const float4*)&Whh0[lane * HH + 4 * i];
        float4 v1 = *(const float4*)&Wih1[lane * HH + 4 * i];
        float4 v2 = *(const float4*)&Whh1[lane * HH + 4 * i];
        w0[4 * i + 0] = v0.x; w0[4 * i + 1] = v0.y; w0[4 * i + 2] = v0.z; w0[4 * i + 3] = v0.w;
        wi1[4 * i + 0] = v1.x; wi1[4 * i + 1] = v1.y; wi1[4 * i + 2] = v1.z; wi1[4 * i + 3] = v1.w;
        wh1[4 * i + 0] = v2.x; wh1[4 * i + 1] = v2.y; wh1[4 * i + 2] = v2.z; wh1[4 * i + 3] = v2.w;
    }
    const float bias0 = bih0[lane] + bhh0[lane];
    const float bias1 = bih1[lane] + bhh1[lane];

    shA[w][lane] = g_hT0[b * HH + lane];  // t0[-1] = hT0
    shB[w][lane] = g_hT1[b * HH + lane];  // t1[-1] = hT1
    __syncwarp();

    float* tp = g_ts1 + (long)b * HH + lane;
    const int ST = BB * HH;

    float h0 = 0.0f, h1 = 0.0f;

#pragma unroll 4
    for (int p = 0; p < PP; p++) {
        float m0a = bias0, m0b = 0.0f;
        float m1a = bias1, m1b = 0.0f;
        float m2a = 0.0f, m2b = 0.0f;
#pragma unroll
        for (int k8 = 0; k8 < 4; k8++) {
            float4 a0 = *(const float4*)&shA[w][8 * k8 + 0];
            float4 a1 = *(const float4*)&shA[w][8 * k8 + 4];
            float4 c0 = *(const float4*)&shB[w][8 * k8 + 0];
            float4 c1 = *(const float4*)&shB[w][8 * k8 + 4];
            FMA4(m0a, a0, w0, 8 * k8);     FMA4(m0b, a1, w0, 8 * k8 + 4);
            FMA4(m1a, a0, wi1, 8 * k8);    FMA4(m1b, a1, wi1, 8 * k8 + 4);
            FMA4(m2a, c0, wh1, 8 * k8);    FMA4(m2b, c1, wh1, 8 * k8 + 4);
        }
        h0 = tanhf(m0a + m0b);  // t0[p]
        if (p > 0) {
            h1 = tanhf(m1a + m1b + m2a + m2b);   // t1[p-1]
            tp[(long)(p - 1) * ST] = h1;
        }
        __syncwarp();
        shA[w][lane] = h0;
        if (p > 0) shB[w][lane] = h1;
        __syncwarp();
    }

    // epilogue: t1[P-1] from shA = t0[P-1], shB = t1[P-2]
    {
        float m1a = bias1, m1b = 0.0f, m2a = 0.0f, m2b = 0.0f;
#pragma unroll
        for (int k8 = 0; k8 < 4; k8++) {
            float4 a0 = *(const float4*)&shA[w][8 * k8 + 0];
            float4 a1 = *(const float4*)&shA[w][8 * k8 + 4];
            float4 c0 = *(const float4*)&shB[w][8 * k8 + 0];
            float4 c1 = *(const float4*)&shB[w][8 * k8 + 4];
            FMA4(m1a, a0, wi1, 8 * k8);    FMA4(m1b, a1, wi1, 8 * k8 + 4);
            FMA4(m2a, c0, wh1, 8 * k8);    FMA4(m2b, c1, wh1, 8 * k8 + 4);
        }
        tp[(long)(PP - 1) * ST] = tanhf(m1a + m1b + m2a + m2b);
    }
}

// ============================================================================
// Kernel 4: observation MLP. out[b][e][p] = W2 @ gelu(W1 @ ts1 + b1) + b2
// Tile: 4 b x 16 p = 64 rows per block; 256 threads; grid (45, 128).
// Shared reuse: [Xs 2048 | W1s 2048 | WG 4096 | b1 64 | b2 64]; Ys overlays Xs+W1s,
// G overlays W2 (after W2 -> registers).
// ============================================================================
__global__ __launch_bounds__(256) void k_mlp(const float* __restrict__ W1,
                                             const float* __restrict__ b1,
                                             const float* __restrict__ W2,
                                             const float* __restrict__ b2,
                                             float* __restrict__ out) {
    __shared__ __align__(16) float smem[2048 + 2048 + 4096 + 64 + 64];
    float* Xs = smem;            // [64][32]
    float* W1s = smem + 2048;    // [64][32]
    float* WG = smem + 4096;     // W2 [64][64], then G [64 rows][64 j]
    float* b1s = smem + 8192;
    float* b2s = smem + 8256;
    float* Ys = smem;            // [64 rows][64 e], overlays Xs+W1s

    const int tid = threadIdx.x;
    const int p0 = blockIdx.x * 16;
    const int b0 = blockIdx.y * 4;

    // stage ts1 tile: row r = bl*16 + pl
    for (int i = tid; i < 64 * 32; i += 256) {
        const int r = i >> 5, c = i & 31;
        const int bl = r >> 4, pl = r & 15;
        Xs[i] = g_ts1[((long)(p0 + pl) * BB + (b0 + bl)) * HH + c];
    }
    for (int i = tid; i < 2048; i += 256) W1s[i] = W1[i];
    for (int i = tid; i < 4096; i += 256) WG[i] = W2[i];
    if (tid < 64) { b1s[tid] = b1[tid]; b2s[tid] = b2[tid]; }
    __syncthreads();

    const int lane = tid & 31;
    const int w = tid >> 5;

    // W1 rows j=lane, j=lane+32 into registers
    float w1a[32], w1b[32];
#pragma unroll
    for (int i = 0; i < 8; i++) {
        float4 va = *(const float4*)&W1s[lane * 32 + 4 * i];
        float4 vb = *(const float4*)&W1s[(lane + 32) * 32 + 4 * i];
        w1a[4 * i + 0] = va.x; w1a[4 * i + 1] = va.y; w1a[4 * i + 2] = va.z; w1a[4 * i + 3] = va.w;
        w1b[4 * i + 0] = vb.x; w1b[4 * i + 1] = vb.y; w1b[4 * i + 2] = vb.z; w1b[4 * i + 3] = vb.w;
    }
    const float ba = b1s[lane], bb = b1s[lane + 32];

    // W2 row for output e into registers
    const int ehalf = w & 1, rg = w >> 1;
    const int e = ehalf * 32 + lane;
    float w2r[64];
#pragma unroll
    for (int i = 0; i < 16; i++) {
        float4 v = *(const float4*)&WG[e * 64 + 4 * i];
        w2r[4 * i + 0] = v.x; w2r[4 * i + 1] = v.y; w2r[4 * i + 2] = v.z; w2r[4 * i + 3] = v.w;
    }
    const float ybias = b2s[e];
    __syncthreads();  // everyone finished reading W2 from WG

    // phase 1: warp w computes rows 8w..8w+7, hidden j=lane and lane+32
#pragma unroll
    for (int rr = 0; rr < 8; rr++) {
        const int r = w * 8 + rr;
        float ma = ba, mb = bb;
#pragma unroll
        for (int k4 = 0; k4 < 8; k4++) {
            float4 xv = *(const float4*)&Xs[r * 32 + 4 * k4];  // broadcast
            FMA4(ma, xv, w1a, 4 * k4);
            FMA4(mb, xv, w1b, 4 * k4);
        }
        const float ga = 0.5f * ma * (1.0f + erff(ma * 0.70710678118654752f));
        const float gb = 0.5f * mb * (1.0f + erff(mb * 0.70710678118654752f));
        WG[r * 64 + lane] = ga;
        WG[r * 64 + lane + 32] = gb;
    }
    __syncthreads();

    // phase 2: warp (ehalf, rg) computes rows rg*16..+16 for output e
#pragma unroll
    for (int rr = 0; rr < 16; rr++) {
        const int r = rg * 16 + rr;
        float y = ybias;
#pragma unroll
        for (int j4 = 0; j4 < 16; j4++) {
            float4 gv = *(const float4*)&WG[r * 64 + 4 * j4];  // broadcast
            FMA4(y, gv, w2r, 4 * j4);
        }
        Ys[r * 64 + e] = y;
    }
    __syncthreads();

    // write out[b][e][p] coalesced as float4 along p
    for (int i = tid; i < 1024; i += 256) {
        const int pl4 = i & 3;
        const int ee = (i >> 2) & 63;
        const int bl = i >> 8;
        float4 v;
        v.x = Ys[(bl * 16 + pl4 * 4 + 0) * 64 + ee];
        v.y = Ys[(bl * 16 + pl4 * 4 + 1) * 64 + ee];
        v.z = Ys[(bl * 16 + pl4 * 4 + 2) * 64 + ee];
        v.w = Ys[(bl * 16 + pl4 * 4 + 3) * 64 + ee];
        *(float4*)&out[(long)(b0 + bl) * EE * PP + (long)ee * PP + p0 + pl4 * 4] = v;
    }
}

// ============================================================================
extern "C" void kernel_launch(void* const* d_in, const int* in_sizes, int n_in,
                              void* d_out, int out_size) {
    (void)in_sizes; (void)n_in; (void)out_size;
    const float* x      = (const float*)d_in[0];
    const float* e_Wih0 = (const float*)d_in[1];
    const float* e_Whh0 = (const float*)d_in[2];
    const float* e_bih0 = (const float*)d_in[3];
    const float* e_bhh0 = (const float*)d_in[4];
    const float* e_Wih1 = (const float*)d_in[5];
    const float* e_Whh1 = (const float*)d_in[6];
    const float* e_bih1 = (const float*)d_in[7];
    const float* e_bhh1 = (const float*)d_in[8];
    // d_in[9] = t_Wih0: unused (transition input is zeros)
    const float* t_Whh0 = (const float*)d_in[10];
    const float* t_bih0 = (const float*)d_in[11];
    const float* t_bhh0 = (const float*)d_in[12];
    const float* t_Wih1 = (const float*)d_in[13];
    const float* t_Whh1 = (const float*)d_in[14];
    const float* t_bih1 = (const float*)d_in[15];
    const float* t_bhh1 = (const float*)d_in[16];
    const float* o_W1   = (const float*)d_in[17];
    const float* o_b1   = (const float*)d_in[18];
    const float* o_W2   = (const float*)d_in[19];
    const float* o_b2   = (const float*)d_in[20];
    float* out = (float*)d_out;

    k_z0<<<(BB * TT) / 64, 256>>>(x, e_Wih0, e_bih0, e_bhh0);
    k_enc<<<BB / 4, 128>>>(e_Whh0, e_Wih1, e_Whh1, e_bih1, e_bhh1);
    k_trans<<<BB / 4, 128>>>(t_Whh0, t_bih0, t_bhh0, t_Wih1, t_Whh1, t_bih1, t_bhh1);
    dim3 g(PP / 16, BB / 4);
    k_mlp<<<g, 256>>>(o_W1, o_b1, o_W2, o_b2, out);
}

// round 2
// speedup vs baseline: 1.1760x; 1.1760x over previous
#include <cuda_runtime.h>
#include <math.h>

#define BB 512
#define TT 1024
#define EE 64
#define HH 32
#define PP 720

typedef unsigned long long u64;

// ---------------- scratch (device globals: no allocation allowed) ----------
__device__ float g_z0[(size_t)TT * BB * HH];   // [t][b][h]
__device__ float g_hT0[BB * HH];
__device__ float g_hT1[BB * HH];
__device__ float g_ts1[(size_t)PP * BB * HH];  // [p][b][h]

// ---------------- packed fp32x2 helpers (Blackwell FFMA2) ------------------
__device__ __forceinline__ u64 pk(float a, float b) {
    u64 r; asm("mov.b64 %0, {%1,%2};" : "=l"(r) : "f"(a), "f"(b)); return r;
}
__device__ __forceinline__ float2 upk(u64 v) {
    float2 r; asm("mov.b64 {%0,%1}, %2;" : "=f"(r.x), "=f"(r.y) : "l"(v)); return r;
}
__device__ __forceinline__ u64 fma2(u64 a, u64 b, u64 c) {
    u64 d; asm("fma.rn.f32x2 %0, %1, %2, %3;" : "=l"(d) : "l"(a), "l"(b), "l"(c)); return d;
}
__device__ __forceinline__ u64 add2(u64 a, u64 b) {
    u64 d; asm("add.rn.f32x2 %0, %1, %2;" : "=l"(d) : "l"(a), "l"(b)); return d;
}

// fast tanh: exp2-based, rel err ~1e-6 (budget is 1e-3)
__device__ __forceinline__ float ftanh(float x) {
    float ax = fabsf(x);
    float e = __expf(-2.0f * ax);
    float r = __fdividef(1.0f - e, 1.0f + e);
    return copysignf(r, x);
}

__device__ __forceinline__ float gelu(float x) {
    return 0.5f * x * (1.0f + erff(x * 0.70710678118654752f));
}

// ============================================================================
// Kernel 1: z0[t][b][h] = dot(x[b][t][:], Wih0[h][:]) + (bih0+bhh0)[h]
// grid 8192 x 256; block = 64 (b,t) rows. Weights read from global (L1/L2 hit).
// ============================================================================
__global__ __launch_bounds__(256) void k_z0(const float* __restrict__ x,
                                            const float* __restrict__ Wih0,
                                            const float* __restrict__ bih0,
                                            const float* __restrict__ bhh0) {
    __shared__ __align__(16) float Xs[64 * EE];   // 16 KB

    const int tid = threadIdx.x;
    const long R0 = (long)blockIdx.x * 64;

    {
        const float4* src = (const float4*)(x + R0 * EE);
        float4* dst = (float4*)Xs;
#pragma unroll
        for (int i = 0; i < 4; i++) dst[tid + 256 * i] = src[tid + 256 * i];
    }

    const int h = tid & 31;
    const int rbase = tid >> 5;

    u64 wp[EE / 2];
#pragma unroll
    for (int i = 0; i < EE / 4; i++) {
        float4 wv = *(const float4*)&Wih0[h * EE + 4 * i];
        wp[2 * i + 0] = pk(wv.x, wv.y);
        wp[2 * i + 1] = pk(wv.z, wv.w);
    }
    const float bias = bih0[h] + bhh0[h];
    __syncthreads();

#pragma unroll
    for (int rr = 0; rr < 8; rr++) {
        const int r = rbase + 8 * rr;
        u64 a = pk(bias, 0.0f), b = pk(0.0f, 0.0f);
#pragma unroll
        for (int e4 = 0; e4 < EE / 4; e4++) {
            ulonglong2 xv = *(const ulonglong2*)&Xs[r * EE + 4 * e4];  // broadcast
            a = fma2(xv.x, wp[2 * e4 + 0], a);
            b = fma2(xv.y, wp[2 * e4 + 1], b);
        }
        float2 u = upk(add2(a, b));
        const long R = R0 + r;
        const int bidx = (int)(R >> 10);
        const int t = (int)(R & 1023);
        g_z0[((long)t * BB + bidx) * HH + h] = u.x + u.y;
    }
}

// ============================================================================
// Kernel 2: encoder 2-layer scan. One warp per batch row, layer 1 lags layer 0
// by one step. Packed FFMA2 dots, double-buffered shared (1 syncwarp/step).
// ============================================================================
__global__ __launch_bounds__(128) void k_enc(const float* __restrict__ Whh0,
                                             const float* __restrict__ Wih1,
                                             const float* __restrict__ Whh1,
                                             const float* __restrict__ bih1,
                                             const float* __restrict__ bhh1) {
    __shared__ __align__(16) float shA[2][4][HH];
    __shared__ __align__(16) float shB[2][4][HH];

    const int lane = threadIdx.x & 31;
    const int w = threadIdx.x >> 5;
    const int b = blockIdx.x * 4 + w;

    u64 w0p[16], wi1p[16], wh1p[16];
#pragma unroll
    for (int i = 0; i < 8; i++) {
        float4 v0 = *(const float4*)&Whh0[lane * HH + 4 * i];
        float4 v1 = *(const float4*)&Wih1[lane * HH + 4 * i];
        float4 v2 = *(const float4*)&Whh1[lane * HH + 4 * i];
        w0p[2 * i] = pk(v0.x, v0.y);  w0p[2 * i + 1] = pk(v0.z, v0.w);
        wi1p[2 * i] = pk(v1.x, v1.y); wi1p[2 * i + 1] = pk(v1.z, v1.w);
        wh1p[2 * i] = pk(v2.x, v2.y); wh1p[2 * i + 1] = pk(v2.z, v2.w);
    }
    const float bias1 = bih1[lane] + bhh1[lane];

    shA[0][w][lane] = 0.0f;
    shB[0][w][lane] = 0.0f;
    __syncwarp();

    const float* zp = g_z0 + (long)b * HH + lane;
    const int ST = BB * HH;

    float zbuf[4];
#pragma unroll
    for (int i = 0; i < 4; i++) zbuf[i] = zp[(long)i * ST];

    float h0n = 0.0f;

#pragma unroll 2
    for (int t = 0; t < TT; t++) {
        const int cur = t & 1, nxt = cur ^ 1;
        const float z = zbuf[t & 3];
        if (t + 4 < TT) zbuf[t & 3] = zp[(long)(t + 4) * ST];

        u64 m0a = pk(z, 0.0f), m0b = pk(0.0f, 0.0f);
        u64 m1a = pk(bias1, 0.0f), m1b = pk(0.0f, 0.0f);
        u64 m2a = pk(0.0f, 0.0f), m2b = pk(0.0f, 0.0f);
#pragma unroll
        for (int q = 0; q < 8; q++) {
            ulonglong2 a = *(const ulonglong2*)&shA[cur][w][4 * q];
            ulonglong2 c = *(const ulonglong2*)&shB[cur][w][4 * q];
            m0a = fma2(a.x, w0p[2 * q], m0a);   m0b = fma2(a.y, w0p[2 * q + 1], m0b);
            m1a = fma2(a.x, wi1p[2 * q], m1a);  m1b = fma2(a.y, wi1p[2 * q + 1], m1b);
            m2a = fma2(c.x, wh1p[2 * q], m2a);  m2b = fma2(c.y, wh1p[2 * q + 1], m2b);
        }
        float2 r0 = upk(add2(m0a, m0b));
        float2 r1 = upk(add2(m1a, m1b));
        float2 r2 = upk(add2(m2a, m2b));
        h0n = ftanh(r0.x + r0.y);
        const float h1n = (t > 0) ? ftanh(r1.x + r1.y + r2.x + r2.y) : 0.0f;

        shA[nxt][w][lane] = h0n;   // h0[t]
        shB[nxt][w][lane] = h1n;   // h1[t-1]
        __syncwarp();
    }

    // epilogue: h1[T-1] from shA[0]=h0[T-1], shB[0]=h1[T-2]   (TT even)
    {
        u64 m1a = pk(bias1, 0.0f), m1b = pk(0.0f, 0.0f);
        u64 m2a = pk(0.0f, 0.0f), m2b = pk(0.0f, 0.0f);
#pragma unroll
        for (int q = 0; q < 8; q++) {
            ulonglong2 a = *(const ulonglong2*)&shA[0][w][4 * q];
            ulonglong2 c = *(const ulonglong2*)&shB[0][w][4 * q];
            m1a = fma2(a.x, wi1p[2 * q], m1a);  m1b = fma2(a.y, wi1p[2 * q + 1], m1b);
            m2a = fma2(c.x, wh1p[2 * q], m2a);  m2b = fma2(c.y, wh1p[2 * q + 1], m2b);
        }
        float2 r1 = upk(add2(m1a, m1b));
        float2 r2 = upk(add2(m2a, m2b));
        g_hT0[b * HH + lane] = h0n;
        g_hT1[b * HH + lane] = ftanh(r1.x + r1.y + r2.x + r2.y);
    }
}

// ============================================================================
// Kernel 3: transition 2-layer scan (layer-0 input = const bias).
// ============================================================================
__global__ __launch_bounds__(128) void k_trans(const float* __restrict__ Whh0,
                                               const float* __restrict__ bih0,
                                               const float* __restrict__ bhh0,
                                               const float* __restrict__ Wih1,
                                               const float* __restrict__ Whh1,
                                               const float* __restrict__ bih1,
                                               const float* __restrict__ bhh1) {
    __shared__ __align__(16) float shA[2][4][HH];
    __shared__ __align__(16) float shB[2][4][HH];

    const int lane = threadIdx.x & 31;
    const int w = threadIdx.x >> 5;
    const int b = blockIdx.x * 4 + w;

    u64 w0p[16], wi1p[16], wh1p[16];
#pragma unroll
    for (int i = 0; i < 8; i++) {
        float4 v0 = *(const float4*)&Whh0[lane * HH + 4 * i];
        float4 v1 = *(const float4*)&Wih1[lane * HH + 4 * i];
        float4 v2 = *(const float4*)&Whh1[lane * HH + 4 * i];
        w0p[2 * i] = pk(v0.x, v0.y);  w0p[2 * i + 1] = pk(v0.z, v0.w);
        wi1p[2 * i] = pk(v1.x, v1.y); wi1p[2 * i + 1] = pk(v1.z, v1.w);
        wh1p[2 * i] = pk(v2.x, v2.y); wh1p[2 * i + 1] = pk(v2.z, v2.w);
    }
    const float bias0 = bih0[lane] + bhh0[lane];
    const float bias1 = bih1[lane] + bhh1[lane];

    shA[0][w][lane] = g_hT0[b * HH + lane];
    shB[0][w][lane] = g_hT1[b * HH + lane];
    __syncwarp();

    float* tp = g_ts1 + (long)b * HH + lane;
    const int ST = BB * HH;

#pragma unroll 2
    for (int p = 0; p < PP; p++) {
        const int cur = p & 1, nxt = cur ^ 1;

        u64 m0a = pk(bias0, 0.0f), m0b = pk(0.0f, 0.0f);
        u64 m1a = pk(bias1, 0.0f), m1b = pk(0.0f, 0.0f);
        u64 m2a = pk(0.0f, 0.0f), m2b = pk(0.0f, 0.0f);
#pragma unroll
        for (int q = 0; q < 8; q++) {
            ulonglong2 a = *(const ulonglong2*)&shA[cur][w][4 * q];
            ulonglong2 c = *(const ulonglong2*)&shB[cur][w][4 * q];
            m0a = fma2(a.x, w0p[2 * q], m0a);   m0b = fma2(a.y, w0p[2 * q + 1], m0b);
            m1a = fma2(a.x, wi1p[2 * q], m1a);  m1b = fma2(a.y, wi1p[2 * q + 1], m1b);
            m2a = fma2(c.x, wh1p[2 * q], m2a);  m2b = fma2(c.y, wh1p[2 * q + 1], m2b);
        }
        float2 r0 = upk(add2(m0a, m0b));
        float2 r1 = upk(add2(m1a, m1b));
        float2 r2 = upk(add2(m2a, m2b));
        const float h0n = ftanh(r0.x + r0.y);                    // t0[p]
        const float h1n = ftanh(r1.x + r1.y + r2.x + r2.y);      // t1[p-1]
        if (p > 0) tp[(long)(p - 1) * ST] = h1n;

        shA[nxt][w][lane] = h0n;
        shB[nxt][w][lane] = (p > 0) ? h1n : shB[0][w][lane];
        __syncwarp();
    }

    // epilogue: t1[P-1] from shA[0]=t0[P-1], shB[0]=t1[P-2]   (PP even)
    {
        u64 m1a = pk(bias1, 0.0f), m1b = pk(0.0f, 0.0f);
        u64 m2a = pk(0.0f, 0.0f), m2b = pk(0.0f, 0.0f);
#pragma unroll
        for (int q = 0; q < 8; q++) {
            ulonglong2 a = *(const ulonglong2*)&shA[0][w][4 * q];
            ulonglong2 c = *(const ulonglong2*)&shB[0][w][4 * q];
            m1a = fma2(a.x, wi1p[2 * q], m1a);  m1b = fma2(a.y, wi1p[2 * q + 1], m1b);
            m2a = fma2(c.x, wh1p[2 * q], m2a);  m2b = fma2(c.y, wh1p[2 * q + 1], m2b);
        }
        float2 r1 = upk(add2(m1a, m1b));
        float2 r2 = upk(add2(m2a, m2b));
        tp[(long)(PP - 1) * ST] = ftanh(r1.x + r1.y + r2.x + r2.y);
    }
}

// ============================================================================
// Kernel 4: observation MLP as tiled GEMM chain.
// Block tile: 128 rows (16 p x 8 b) x 64 cols. 256 threads, 8x4 outputs/thread.
// Row index r = bl*16 + pl  =>  thread's 8 rows are 8 consecutive p values.
// ============================================================================
#define MLP_SMEM_FLOATS (4096 + 2304 + 4352 + 8192 + 128)

__global__ __launch_bounds__(256) void k_mlp(const float* __restrict__ W1,
                                             const float* __restrict__ b1,
                                             const float* __restrict__ W2,
                                             const float* __restrict__ b2,
                                             float* __restrict__ out) {
    extern __shared__ __align__(16) float sm[];
    float* Xs  = sm;                  // [128][32]
    float* W1s = sm + 4096;           // [64][36]  (pad 36 -> 2-way conflicts max)
    float* W2s = sm + 6400;           // [64][68]
    float* Gs  = sm + 10752;          // [128][64]
    float* b1s = sm + 18944;
    float* b2s = sm + 19008;

    const int tid = threadIdx.x;
    const int tx = tid & 15;          // col group: e = 4*tx + j
    const int ty = tid >> 4;          // row group: rows 8*ty .. 8*ty+7
    const int c0 = 4 * tx;
    const int p0 = blockIdx.x * 16;
    const int b0 = blockIdx.y * 8;

    // stage ts1 tile  (r = bl*16 + pl)
    for (int i4 = tid; i4 < 1024; i4 += 256) {
        const int r = i4 >> 3, c4 = i4 & 7;
        const int bl = r >> 4, pl = r & 15;
        ((float4*)Xs)[i4] =
            *(const float4*)&g_ts1[((long)(p0 + pl) * BB + (b0 + bl)) * HH + 4 * c4];
    }
    for (int i4 = tid; i4 < 512; i4 += 256) {      // W1 [64][32] -> [64][36]
        const int j = i4 >> 3, k4 = i4 & 7;
        ((float4*)W1s)[j * 9 + k4] = ((const float4*)W1)[i4];
    }
    for (int i4 = tid; i4 < 1024; i4 += 256) {     // W2 [64][64] -> [64][68]
        const int e = i4 >> 4, j4 = i4 & 15;
        ((float4*)W2s)[e * 17 + j4] = ((const float4*)W2)[i4];
    }
    if (tid < 64) b1s[tid] = b1[tid];
    else if (tid < 128) b2s[tid - 64] = b2[tid - 64];
    __syncthreads();

    // ---------------- phase 1: G = gelu(X @ W1^T + b1) ----------------
    u64 acc[8][4];
#pragma unroll
    for (int i = 0; i < 8; i++)
#pragma unroll
        for (int j = 0; j < 4; j++) acc[i][j] = pk(b1s[c0 + j], 0.0f);

#pragma unroll
    for (int k4 = 0; k4 < 8; k4++) {
        ulonglong2 wv[4];
#pragma unroll
        for (int j = 0; j < 4; j++)
            wv[j] = *(const ulonglong2*)&W1s[(c0 + j) * 36 + 4 * k4];
#pragma unroll
        for (int i = 0; i < 8; i++) {
            ulonglong2 xv = *(const ulonglong2*)&Xs[(8 * ty + i) * 32 + 4 * k4];
#pragma unroll
            for (int j = 0; j < 4; j++) {
                acc[i][j] = fma2(xv.x, wv[j].x, acc[i][j]);
                acc[i][j] = fma2(xv.y, wv[j].y, acc[i][j]);
            }
        }
    }

#pragma unroll
    for (int i = 0; i < 8; i++) {
        float4 g;
        float2 u0 = upk(acc[i][0]); g.x = gelu(u0.x + u0.y);
        float2 u1 = upk(acc[i][1]); g.y = gelu(u1.x + u1.y);
        float2 u2 = upk(acc[i][2]); g.z = gelu(u2.x + u2.y);
        float2 u3 = upk(acc[i][3]); g.w = gelu(u3.x + u3.y);
        ((float4*)&Gs[(8 * ty + i) * 64])[tx] = g;
    }
    __syncthreads();

    // ---------------- phase 2: Y = G @ W2^T + b2 ----------------
#pragma unroll
    for (int i = 0; i < 8; i++)
#pragma unroll
        for (int j = 0; j < 4; j++) acc[i][j] = pk(b2s[c0 + j], 0.0f);

#pragma unroll
    for (int k4 = 0; k4 < 16; k4++) {
        ulonglong2 wv[4];
#pragma unroll
        for (int j = 0; j < 4; j++)
            wv[j] = *(const ulonglong2*)&W2s[(c0 + j) * 68 + 4 * k4];
#pragma unroll
        for (int i = 0; i < 8; i++) {
            ulonglong2 gv = *(const ulonglong2*)&Gs[(8 * ty + i) * 64 + 4 * k4];
#pragma unroll
            for (int j = 0; j < 4; j++) {
                acc[i][j] = fma2(gv.x, wv[j].x, acc[i][j]);
                acc[i][j] = fma2(gv.y, wv[j].y, acc[i][j]);
            }
        }
    }

    // write out[b][e][p]: thread rows = 8 consecutive p, float4 along p
    float y[8][4];
#pragma unroll
    for (int i = 0; i < 8; i++)
#pragma unroll
        for (int j = 0; j < 4; j++) {
            float2 u = upk(acc[i][j]);
            y[i][j] = u.x + u.y;
        }

    const int bl = ty >> 1;
    const int plb = (ty & 1) * 8;
    float* ob = out + (long)(b0 + bl) * EE * PP + p0 + plb;
#pragma unroll
    for (int j = 0; j < 4; j++) {
#pragma unroll
        for (int q = 0; q < 2; q++) {
            float4 v;
            v.x = y[4 * q + 0][j]; v.y = y[4 * q + 1][j];
            v.z = y[4 * q + 2][j]; v.w = y[4 * q + 3][j];
            *(float4*)&ob[(long)(c0 + j) * PP + 4 * q] = v;
        }
    }
}

// ============================================================================
extern "C" void kernel_launch(void* const* d_in, const int* in_sizes, int n_in,
                              void* d_out, int out_size) {
    (void)in_sizes; (void)n_in; (void)out_size;
    const float* x      = (const float*)d_in[0];
    const float* e_Wih0 = (const float*)d_in[1];
    const float* e_Whh0 = (const float*)d_in[2];
    const float* e_bih0 = (const float*)d_in[3];
    const float* e_bhh0 = (const float*)d_in[4];
    const float* e_Wih1 = (const float*)d_in[5];
    const float* e_Whh1 = (const float*)d_in[6];
    const float* e_bih1 = (const float*)d_in[7];
    const float* e_bhh1 = (const float*)d_in[8];
    // d_in[9] = t_Wih0: unused (transition input is zeros)
    const float* t_Whh0 = (const float*)d_in[10];
    const float* t_bih0 = (const float*)d_in[11];
    const float* t_bhh0 = (const float*)d_in[12];
    const float* t_Wih1 = (const float*)d_in[13];
    const float* t_Whh1 = (const float*)d_in[14];
    const float* t_bih1 = (const float*)d_in[15];
    const float* t_bhh1 = (const float*)d_in[16];
    const float* o_W1   = (const float*)d_in[17];
    const float* o_b1   = (const float*)d_in[18];
    const float* o_W2   = (const float*)d_in[19];
    const float* o_b2   = (const float*)d_in[20];
    float* out = (float*)d_out;

    cudaFuncSetAttribute(k_mlp, cudaFuncAttributeMaxDynamicSharedMemorySize,
                         MLP_SMEM_FLOATS * 4);

    k_z0<<<(BB * TT) / 64, 256>>>(x, e_Wih0, e_bih0, e_bhh0);
    k_enc<<<BB / 4, 128>>>(e_Whh0, e_Wih1, e_Whh1, e_bih1, e_bhh1);
    k_trans<<<BB / 4, 128>>>(t_Whh0, t_bih0, t_bhh0, t_Wih1, t_Whh1, t_bih1, t_bhh1);
    dim3 g(PP / 16, BB / 8);
    k_mlp<<<g, 256, MLP_SMEM_FLOATS * 4>>>(o_W1, o_b1, o_W2, o_b2, out);
}

// round 3
// speedup vs baseline: 1.4171x; 1.2050x over previous
#include <cuda_runtime.h>
#include <math.h>

#define BB 512
#define TT 1024
#define EE 64
#define HH 32
#define PP 720

typedef unsigned long long u64;

// ---------------- scratch (device globals: no allocation allowed) ----------
__device__ float g_z0[(size_t)TT * BB * HH];   // [t][b][h]
__device__ float g_hT0[BB * HH];
__device__ float g_hT1[BB * HH];
__device__ float g_ts1[(size_t)PP * BB * HH];  // [p][b][h]

// ---------------- packed fp32x2 helpers (Blackwell FFMA2) ------------------
__device__ __forceinline__ u64 pk(float a, float b) {
    u64 r; asm("mov.b64 %0, {%1,%2};" : "=l"(r) : "f"(a), "f"(b)); return r;
}
__device__ __forceinline__ float2 upk(u64 v) {
    float2 r; asm("mov.b64 {%0,%1}, %2;" : "=f"(r.x), "=f"(r.y) : "l"(v)); return r;
}
__device__ __forceinline__ u64 fma2(u64 a, u64 b, u64 c) {
    u64 d; asm("fma.rn.f32x2 %0, %1, %2, %3;" : "=l"(d) : "l"(a), "l"(b), "l"(c)); return d;
}
__device__ __forceinline__ u64 add2(u64 a, u64 b) {
    u64 d; asm("add.rn.f32x2 %0, %1, %2;" : "=l"(d) : "l"(a), "l"(b)); return d;
}

// fast tanh: tanh(x) = 1 - 2/(1+exp(2x)); exact at both saturations.
// ex2.approx rel err ~2^-22, div.approx ~2 ulp -> plenty for 1e-3 budget.
__device__ __forceinline__ float ftanh(float x) {
    float e;
    asm("ex2.approx.f32 %0, %1;" : "=f"(e) : "f"(x * 2.885390081777927f));
    return 1.0f - __fdividef(2.0f, e + 1.0f);
}

__device__ __forceinline__ float gelu(float x) {
    return 0.5f * x * (1.0f + erff(x * 0.70710678118654752f));
}

// ============================================================================
// Kernel 1: z0[t][b][h] = dot(x[b][t][:], Wih0[h][:]) + (bih0+bhh0)[h]
// ============================================================================
__global__ __launch_bounds__(256) void k_z0(const float* __restrict__ x,
                                            const float* __restrict__ Wih0,
                                            const float* __restrict__ bih0,
                                            const float* __restrict__ bhh0) {
    __shared__ __align__(16) float Xs[64 * EE];   // 16 KB

    const int tid = threadIdx.x;
    const long R0 = (long)blockIdx.x * 64;

    {
        const float4* src = (const float4*)(x + R0 * EE);
        float4* dst = (float4*)Xs;
#pragma unroll
        for (int i = 0; i < 4; i++) dst[tid + 256 * i] = src[tid + 256 * i];
    }

    const int h = tid & 31;
    const int rbase = tid >> 5;

    u64 wp[EE / 2];
#pragma unroll
    for (int i = 0; i < EE / 4; i++) {
        float4 wv = *(const float4*)&Wih0[h * EE + 4 * i];
        wp[2 * i + 0] = pk(wv.x, wv.y);
        wp[2 * i + 1] = pk(wv.z, wv.w);
    }
    const float bias = bih0[h] + bhh0[h];
    __syncthreads();

#pragma unroll
    for (int rr = 0; rr < 8; rr++) {
        const int r = rbase + 8 * rr;
        u64 a = pk(bias, 0.0f), b = pk(0.0f, 0.0f);
#pragma unroll
        for (int e4 = 0; e4 < EE / 4; e4++) {
            ulonglong2 xv = *(const ulonglong2*)&Xs[r * EE + 4 * e4];  // broadcast
            a = fma2(xv.x, wp[2 * e4 + 0], a);
            b = fma2(xv.y, wp[2 * e4 + 1], b);
        }
        float2 u = upk(add2(a, b));
        const long R = R0 + r;
        const int bidx = (int)(R >> 10);
        const int t = (int)(R & 1023);
        g_z0[((long)t * BB + bidx) * HH + h] = u.x + u.y;
    }
}

// ---------------- shared scan-step macro (4-acc split chains) --------------
// Computes m0 = z + w0.hA, m1 = bias1 + wi1.hA, m2 = wh1.hB from shared bufs.
#define SCAN_DOT(CUR)                                                          \
    u64 m0a = pk(zin, 0.0f), m0b = ZZ, m0c = ZZ, m0d = ZZ;                     \
    u64 m1a = pk(bias1, 0.0f), m1b = ZZ, m1c = ZZ, m1d = ZZ;                   \
    u64 m2a = ZZ, m2b = ZZ, m2c = ZZ, m2d = ZZ;                                \
    _Pragma("unroll")                                                          \
    for (int q = 0; q < 4; q++) {                                              \
        ulonglong2 a0 = *(const ulonglong2*)&shA[CUR][w][8 * q];               \
        ulonglong2 a1 = *(const ulonglong2*)&shA[CUR][w][8 * q + 4];           \
        ulonglong2 c0 = *(const ulonglong2*)&shB[CUR][w][8 * q];               \
        ulonglong2 c1 = *(const ulonglong2*)&shB[CUR][w][8 * q + 4];           \
        m0a = fma2(a0.x, w0p[4 * q + 0], m0a);                                 \
        m0b = fma2(a0.y, w0p[4 * q + 1], m0b);                                 \
        m0c = fma2(a1.x, w0p[4 * q + 2], m0c);                                 \
        m0d = fma2(a1.y, w0p[4 * q + 3], m0d);                                 \
        m1a = fma2(a0.x, wi1p[4 * q + 0], m1a);                                \
        m1b = fma2(a0.y, wi1p[4 * q + 1], m1b);                                \
        m1c = fma2(a1.x, wi1p[4 * q + 2], m1c);                                \
        m1d = fma2(a1.y, wi1p[4 * q + 3], m1d);                                \
        m2a = fma2(c0.x, wh1p[4 * q + 0], m2a);                                \
        m2b = fma2(c0.y, wh1p[4 * q + 1], m2b);                                \
        m2c = fma2(c1.x, wh1p[4 * q + 2], m2c);                                \
        m2d = fma2(c1.y, wh1p[4 * q + 3], m2d);                                \
    }                                                                          \
    float2 r0 = upk(add2(add2(m0a, m0b), add2(m0c, m0d)));                     \
    float2 r1 = upk(add2(add2(m1a, m1b), add2(m1c, m1d)));                     \
    float2 r2 = upk(add2(add2(m2a, m2b), add2(m2c, m2d)));

#define LOAD_SCAN_WEIGHTS(W0, WI1, WH1)                                        \
    u64 w0p[16], wi1p[16], wh1p[16];                                           \
    _Pragma("unroll")                                                          \
    for (int i = 0; i < 8; i++) {                                              \
        float4 v0 = *(const float4*)&(W0)[lane * HH + 4 * i];                  \
        float4 v1 = *(const float4*)&(WI1)[lane * HH + 4 * i];                 \
        float4 v2 = *(const float4*)&(WH1)[lane * HH + 4 * i];                 \
        w0p[2 * i] = pk(v0.x, v0.y);  w0p[2 * i + 1] = pk(v0.z, v0.w);         \
        wi1p[2 * i] = pk(v1.x, v1.y); wi1p[2 * i + 1] = pk(v1.z, v1.w);        \
        wh1p[2 * i] = pk(v2.x, v2.y); wh1p[2 * i + 1] = pk(v2.z, v2.w);        \
    }

// ============================================================================
// Kernel 2: encoder 2-layer scan, layer 1 lagged one step. unroll-8 body,
// depth-8 z prefetch (all indices compile-time constant).
// ============================================================================
__global__ __launch_bounds__(128) void k_enc(const float* __restrict__ Whh0,
                                             const float* __restrict__ Wih1,
                                             const float* __restrict__ Whh1,
                                             const float* __restrict__ bih1,
                                             const float* __restrict__ bhh1) {
    __shared__ __align__(16) float shA[2][4][HH];
    __shared__ __align__(16) float shB[2][4][HH];

    const int lane = threadIdx.x & 31;
    const int w = threadIdx.x >> 5;
    const int b = blockIdx.x * 4 + w;
    const u64 ZZ = pk(0.0f, 0.0f);

    LOAD_SCAN_WEIGHTS(Whh0, Wih1, Whh1)
    const float bias1 = bih1[lane] + bhh1[lane];

    shA[0][w][lane] = 0.0f;
    shB[0][w][lane] = 0.0f;
    __syncwarp();

    const float* zp = g_z0 + (long)b * HH + lane;
    const int ST = BB * HH;

    float zbuf[8];
#pragma unroll
    for (int i = 0; i < 8; i++) zbuf[i] = zp[(long)i * ST];

    float h0last = 0.0f;

    for (int t0 = 0; t0 < TT; t0 += 8) {
        const bool pf = (t0 + 8 < TT);
#pragma unroll
        for (int u = 0; u < 8; u++) {
            const int t = t0 + u;
            const int cur = u & 1, nxt = cur ^ 1;
            const float zin = zbuf[u];
            if (pf) zbuf[u] = zp[(long)(t + 8) * ST];

            SCAN_DOT(cur)

            const float h0v = ftanh(r0.x + r0.y);
            const float h1v = (t > 0) ? ftanh((r1.x + r1.y) + (r2.x + r2.y)) : 0.0f;
            shA[nxt][w][lane] = h0v;   // h0[t]
            shB[nxt][w][lane] = h1v;   // h1[t-1]
            h0last = h0v;
            __syncwarp();
        }
    }

    // epilogue: h1[T-1] from shA[0]=h0[T-1], shB[0]=h1[T-2]
    {
        u64 m1a = pk(bias1, 0.0f), m1b = ZZ, m2a = ZZ, m2b = ZZ;
#pragma unroll
        for (int q = 0; q < 8; q++) {
            ulonglong2 a = *(const ulonglong2*)&shA[0][w][4 * q];
            ulonglong2 c = *(const ulonglong2*)&shB[0][w][4 * q];
            m1a = fma2(a.x, wi1p[2 * q], m1a);  m1b = fma2(a.y, wi1p[2 * q + 1], m1b);
            m2a = fma2(c.x, wh1p[2 * q], m2a);  m2b = fma2(c.y, wh1p[2 * q + 1], m2b);
        }
        float2 r1 = upk(add2(m1a, m1b));
        float2 r2 = upk(add2(m2a, m2b));
        g_hT0[b * HH + lane] = h0last;
        g_hT1[b * HH + lane] = ftanh((r1.x + r1.y) + (r2.x + r2.y));
    }
}

// ============================================================================
// Kernel 3: transition 2-layer scan (layer-0 input = const bias). unroll-8.
// ============================================================================
__global__ __launch_bounds__(128) void k_trans(const float* __restrict__ Whh0,
                                               const float* __restrict__ bih0,
                                               const float* __restrict__ bhh0,
                                               const float* __restrict__ Wih1,
                                               const float* __restrict__ Whh1,
                                               const float* __restrict__ bih1,
                                               const float* __restrict__ bhh1) {
    __shared__ __align__(16) float shA[2][4][HH];
    __shared__ __align__(16) float shB[2][4][HH];

    const int lane = threadIdx.x & 31;
    const int w = threadIdx.x >> 5;
    const int b = blockIdx.x * 4 + w;
    const u64 ZZ = pk(0.0f, 0.0f);

    LOAD_SCAN_WEIGHTS(Whh0, Wih1, Whh1)
    const float bias0 = bih0[lane] + bhh0[lane];
    const float bias1 = bih1[lane] + bhh1[lane];
    const float hT1r = g_hT1[b * HH + lane];

    shA[0][w][lane] = g_hT0[b * HH + lane];  // t0[-1]
    shB[0][w][lane] = hT1r;                  // t1[-1]
    __syncwarp();

    float* tp = g_ts1 + (long)b * HH + lane;
    const int ST = BB * HH;

    for (int p0 = 0; p0 < PP; p0 += 8) {
#pragma unroll
        for (int u = 0; u < 8; u++) {
            const int p = p0 + u;
            const int cur = u & 1, nxt = cur ^ 1;
            const float zin = bias0;

            SCAN_DOT(cur)

            const float h0v = ftanh(r0.x + r0.y);                      // t0[p]
            const float h1v = ftanh((r1.x + r1.y) + (r2.x + r2.y));    // t1[p-1]
            if (p > 0) tp[(long)(p - 1) * ST] = h1v;
            shA[nxt][w][lane] = h0v;
            shB[nxt][w][lane] = (p > 0) ? h1v : hT1r;
            __syncwarp();
        }
    }

    // epilogue: t1[P-1] from shA[0]=t0[P-1], shB[0]=t1[P-2]
    {
        u64 m1a = pk(bias1, 0.0f), m1b = ZZ, m2a = ZZ, m2b = ZZ;
#pragma unroll
        for (int q = 0; q < 8; q++) {
            ulonglong2 a = *(const ulonglong2*)&shA[0][w][4 * q];
            ulonglong2 c = *(const ulonglong2*)&shB[0][w][4 * q];
            m1a = fma2(a.x, wi1p[2 * q], m1a);  m1b = fma2(a.y, wi1p[2 * q + 1], m1b);
            m2a = fma2(c.x, wh1p[2 * q], m2a);  m2b = fma2(c.y, wh1p[2 * q + 1], m2b);
        }
        float2 r1 = upk(add2(m1a, m1b));
        float2 r2 = upk(add2(m2a, m2b));
        tp[(long)(PP - 1) * ST] = ftanh((r1.x + r1.y) + (r2.x + r2.y));
    }
}

// ============================================================================
// Kernel 4: observation MLP, tiled GEMM chain. Column remap e = tx + 16*j
// turns the 8-way LDS bank conflicts on weight loads into 2-way.
// ============================================================================
#define MLP_SMEM_FLOATS (4096 + 2304 + 4352 + 8192 + 128)

__global__ __launch_bounds__(256) void k_mlp(const float* __restrict__ W1,
                                             const float* __restrict__ b1,
                                             const float* __restrict__ W2,
                                             const float* __restrict__ b2,
                                             float* __restrict__ out) {
    extern __shared__ __align__(16) float sm[];
    float* Xs  = sm;                  // [128][32]
    float* W1s = sm + 4096;           // [64][36]
    float* W2s = sm + 6400;           // [64][68]
    float* Gs  = sm + 10752;          // [128][64]
    float* b1s = sm + 18944;
    float* b2s = sm + 19008;

    const int tid = threadIdx.x;
    const int tx = tid & 15;          // col: e_j = tx + 16*j
    const int ty = tid >> 4;          // rows 8*ty .. 8*ty+7
    const int p0 = blockIdx.x * 16;
    const int b0 = blockIdx.y * 8;

    for (int i4 = tid; i4 < 1024; i4 += 256) {
        const int r = i4 >> 3, c4 = i4 & 7;
        const int bl = r >> 4, pl = r & 15;
        ((float4*)Xs)[i4] =
            *(const float4*)&g_ts1[((long)(p0 + pl) * BB + (b0 + bl)) * HH + 4 * c4];
    }
    for (int i4 = tid; i4 < 512; i4 += 256) {      // W1 [64][32] -> [64][36]
        const int j = i4 >> 3, k4 = i4 & 7;
        ((float4*)W1s)[j * 9 + k4] = ((const float4*)W1)[i4];
    }
    for (int i4 = tid; i4 < 1024; i4 += 256) {     // W2 [64][64] -> [64][68]
        const int e = i4 >> 4, j4 = i4 & 15;
        ((float4*)W2s)[e * 17 + j4] = ((const float4*)W2)[i4];
    }
    if (tid < 64) b1s[tid] = b1[tid];
    else if (tid < 128) b2s[tid - 64] = b2[tid - 64];
    __syncthreads();

    // ---------------- phase 1: G = gelu(X @ W1^T + b1) ----------------
    u64 acc[8][4];
#pragma unroll
    for (int i = 0; i < 8; i++)
#pragma unroll
        for (int j = 0; j < 4; j++) acc[i][j] = pk(b1s[tx + 16 * j], 0.0f);

#pragma unroll
    for (int k4 = 0; k4 < 8; k4++) {
        ulonglong2 wv[4];
#pragma unroll
        for (int j = 0; j < 4; j++)
            wv[j] = *(const ulonglong2*)&W1s[(tx + 16 * j) * 36 + 4 * k4];
#pragma unroll
        for (int i = 0; i < 8; i++) {
            ulonglong2 xv = *(const ulonglong2*)&Xs[(8 * ty + i) * 32 + 4 * k4];
#pragma unroll
            for (int j = 0; j < 4; j++) {
                acc[i][j] = fma2(xv.x, wv[j].x, acc[i][j]);
                acc[i][j] = fma2(xv.y, wv[j].y, acc[i][j]);
            }
        }
    }

#pragma unroll
    for (int i = 0; i < 8; i++) {
#pragma unroll
        for (int j = 0; j < 4; j++) {
            float2 uj = upk(acc[i][j]);
            Gs[(8 * ty + i) * 64 + tx + 16 * j] = gelu(uj.x + uj.y);
        }
    }
    __syncthreads();

    // ---------------- phase 2: Y = G @ W2^T + b2 ----------------
#pragma unroll
    for (int i = 0; i < 8; i++)
#pragma unroll
        for (int j = 0; j < 4; j++) acc[i][j] = pk(b2s[tx + 16 * j], 0.0f);

#pragma unroll
    for (int k4 = 0; k4 < 16; k4++) {
        ulonglong2 wv[4];
#pragma unroll
        for (int j = 0; j < 4; j++)
            wv[j] = *(const ulonglong2*)&W2s[(tx + 16 * j) * 68 + 4 * k4];
#pragma unroll
        for (int i = 0; i < 8; i++) {
            ulonglong2 gv = *(const ulonglong2*)&Gs[(8 * ty + i) * 64 + 4 * k4];
#pragma unroll
            for (int j = 0; j < 4; j++) {
                acc[i][j] = fma2(gv.x, wv[j].x, acc[i][j]);
                acc[i][j] = fma2(gv.y, wv[j].y, acc[i][j]);
            }
        }
    }

    float y[8][4];
#pragma unroll
    for (int i = 0; i < 8; i++)
#pragma unroll
        for (int j = 0; j < 4; j++) {
            float2 uj = upk(acc[i][j]);
            y[i][j] = uj.x + uj.y;
        }

    const int bl = ty >> 1;
    const int plb = (ty & 1) * 8;
    float* ob = out + (long)(b0 + bl) * EE * PP + p0 + plb;
#pragma unroll
    for (int j = 0; j < 4; j++) {
        const int e = tx + 16 * j;
#pragma unroll
        for (int q = 0; q < 2; q++) {
            float4 v;
            v.x = y[4 * q + 0][j]; v.y = y[4 * q + 1][j];
            v.z = y[4 * q + 2][j]; v.w = y[4 * q + 3][j];
            *(float4*)&ob[(long)e * PP + 4 * q] = v;
        }
    }
}

// ============================================================================
extern "C" void kernel_launch(void* const* d_in, const int* in_sizes, int n_in,
                              void* d_out, int out_size) {
    (void)in_sizes; (void)n_in; (void)out_size;
    const float* x      = (const float*)d_in[0];
    const float* e_Wih0 = (const float*)d_in[1];
    const float* e_Whh0 = (const float*)d_in[2];
    const float* e_bih0 = (const float*)d_in[3];
    const float* e_bhh0 = (const float*)d_in[4];
    const float* e_Wih1 = (const float*)d_in[5];
    const float* e_Whh1 = (const float*)d_in[6];
    const float* e_bih1 = (const float*)d_in[7];
    const float* e_bhh1 = (const float*)d_in[8];
    // d_in[9] = t_Wih0: unused (transition input is zeros)
    const float* t_Whh0 = (const float*)d_in[10];
    const float* t_bih0 = (const float*)d_in[11];
    const float* t_bhh0 = (const float*)d_in[12];
    const float* t_Wih1 = (const float*)d_in[13];
    const float* t_Whh1 = (const float*)d_in[14];
    const float* t_bih1 = (const float*)d_in[15];
    const float* t_bhh1 = (const float*)d_in[16];
    const float* o_W1   = (const float*)d_in[17];
    const float* o_b1   = (const float*)d_in[18];
    const float* o_W2   = (const float*)d_in[19];
    const float* o_b2   = (const float*)d_in[20];
    float* out = (float*)d_out;

    cudaFuncSetAttribute(k_mlp, cudaFuncAttributeMaxDynamicSharedMemorySize,
                         MLP_SMEM_FLOATS * 4);

    k_z0<<<(BB * TT) / 64, 256>>>(x, e_Wih0, e_bih0, e_bhh0);
    k_enc<<<BB / 4, 128>>>(e_Whh0, e_Wih1, e_Whh1, e_bih1, e_bhh1);
    k_trans<<<BB / 4, 128>>>(t_Whh0, t_bih0, t_bhh0, t_Wih1, t_Whh1, t_bih1, t_bhh1);
    dim3 g(PP / 16, BB / 8);
    k_mlp<<<g, 256, MLP_SMEM_FLOATS * 4>>>(o_W1, o_b1, o_W2, o_b2, out);
}